// round 1
// baseline (speedup 1.0000x reference)
#include <cuda_runtime.h>
#include <math.h>

#define Bsz 2
#define Tsz 2048
#define Csz 1024
#define Hn  16
#define HDd 64

// Scratch (static device arrays — allocation-free per harness rules)
__device__ float g_qkv[Bsz * Tsz * 3 * Csz];      // [B*T, 3C]
__device__ float g_q[Bsz * Hn * Tsz * HDd];       // [B,H,T,HD] rope'd
__device__ float g_k[Bsz * Hn * Tsz * HDd];
__device__ float g_v[Bsz * Hn * Tsz * HDd];
__device__ float g_y[Bsz * Tsz * Csz];            // [B,T,C] attention out

// ---------------------------------------------------------------------------
// SGEMM: C[M,N] = A[M,K] @ B[K,N] + bias[N]
// 64x64 block tile, BK=16, 16x16 threads, 4x4 register micro-tile.
// ---------------------------------------------------------------------------
__global__ void sgemm_bias(const float* __restrict__ A,
                           const float* __restrict__ Bm,
                           const float* __restrict__ bias,
                           float* __restrict__ Cm,
                           int M, int N, int K) {
    __shared__ float As[16][64];   // transposed A tile
    __shared__ float Bs[16][64];

    const int tid = threadIdx.x;
    const int tx = tid & 15;
    const int ty = tid >> 4;
    const int m0 = blockIdx.y * 64;
    const int n0 = blockIdx.x * 64;

    float acc[4][4] = {};

    for (int k0 = 0; k0 < K; k0 += 16) {
        // A tile: 64 rows x 16 cols = 256 float4 (1 per thread), store transposed
        {
            const int ar  = tid >> 2;
            const int ac4 = tid & 3;
            float4 a = *(const float4*)&A[(size_t)(m0 + ar) * K + k0 + ac4 * 4];
            As[ac4 * 4 + 0][ar] = a.x;
            As[ac4 * 4 + 1][ar] = a.y;
            As[ac4 * 4 + 2][ar] = a.z;
            As[ac4 * 4 + 3][ar] = a.w;
        }
        // B tile: 16 rows x 64 cols = 256 float4 (1 per thread)
        {
            const int br  = tid >> 4;
            const int bc4 = tid & 15;
            *(float4*)&Bs[br][bc4 * 4] =
                *(const float4*)&Bm[(size_t)(k0 + br) * N + n0 + bc4 * 4];
        }
        __syncthreads();

        #pragma unroll
        for (int kk = 0; kk < 16; kk++) {
            float4 a4 = *(const float4*)&As[kk][ty * 4];
            float4 b4 = *(const float4*)&Bs[kk][tx * 4];
            float av[4] = {a4.x, a4.y, a4.z, a4.w};
            float bv[4] = {b4.x, b4.y, b4.z, b4.w};
            #pragma unroll
            for (int i = 0; i < 4; i++)
                #pragma unroll
                for (int j = 0; j < 4; j++)
                    acc[i][j] += av[i] * bv[j];
        }
        __syncthreads();
    }

    float4 bb = *(const float4*)&bias[n0 + tx * 4];
    float bv[4] = {bb.x, bb.y, bb.z, bb.w};
    #pragma unroll
    for (int i = 0; i < 4; i++) {
        float4 o;
        o.x = acc[i][0] + bv[0];
        o.y = acc[i][1] + bv[1];
        o.z = acc[i][2] + bv[2];
        o.w = acc[i][3] + bv[3];
        *(float4*)&Cm[(size_t)(m0 + ty * 4 + i) * N + n0 + tx * 4] = o;
    }
}

// ---------------------------------------------------------------------------
// RoPE + split + transpose: g_qkv[B*T,3C] -> g_q/g_k (rope'd), g_v  as [B,H,T,HD]
// One thread per (b,t,h,d2), d2 in [0,32) handles the rotation pair (d2, d2+32).
// ---------------------------------------------------------------------------
__global__ void rope_split_kernel(const float* __restrict__ qkv) {
    const int idx = blockIdx.x * blockDim.x + threadIdx.x;  // 2^21 total
    const int d2 = idx & 31;
    const int h  = (idx >> 5) & 15;
    const int t  = (idx >> 9) & 2047;
    const int b  = idx >> 20;

    const float* base = qkv + (size_t)(b * Tsz + t) * (3 * Csz);
    const int off = h * HDd + d2;

    const float qf = base[off],           qs = base[off + 32];
    const float kf = base[Csz + off],     ks = base[Csz + off + 32];
    const float vf = base[2 * Csz + off], vs = base[2 * Csz + off + 32];

    // timescale = 10000^(d2/32); angle = t / timescale
    const float inv_ts = powf(10000.0f, -(float)d2 * (1.0f / 32.0f));
    const float ang = (float)t * inv_ts;
    float sn, cs;
    sincosf(ang, &sn, &cs);

    const size_t o = (size_t)((b * Hn + h) * Tsz + t) * HDd + d2;
    g_q[o]      = qf * cs - qs * sn;
    g_q[o + 32] = qs * cs + qf * sn;
    g_k[o]      = kf * cs - ks * sn;
    g_k[o + 32] = ks * cs + kf * sn;
    g_v[o]      = vf;
    g_v[o + 32] = vs;
}

// ---------------------------------------------------------------------------
// Flash attention (fp32, online softmax, causal).
// Block = 256 threads = 64 q-rows x 4 threads. Q row in registers.
// K/V tiles in smem padded to 68 floats/row (conflict-free float4 reads,
// 16B-aligned rows). P tile padded to 65 floats/row.
// ---------------------------------------------------------------------------
#define KV_PAD 68
#define P_PAD  65

__global__ void flash_attn_kernel(const float* __restrict__ Q,
                                  const float* __restrict__ K,
                                  const float* __restrict__ V,
                                  float* __restrict__ Y) {
    extern __shared__ float sm[];
    float (*Ks)[KV_PAD] = (float(*)[KV_PAD])sm;
    float (*Vs)[KV_PAD] = (float(*)[KV_PAD])(sm + 64 * KV_PAD);
    float (*Ps)[P_PAD]  = (float(*)[P_PAD]) (sm + 2 * 64 * KV_PAD);

    const int tid   = threadIdx.x;
    const int row   = tid >> 2;       // 0..63
    const int lane4 = tid & 3;        // 0..3
    const int qt = blockIdx.x;        // q tile (0..31)
    const int h  = blockIdx.y;
    const int b  = blockIdx.z;
    const int qrow = qt * 64 + row;

    const size_t bh = (size_t)(b * Hn + h) * Tsz;

    // Q row -> registers (64 floats)
    float4 qreg[16];
    const float4* qp = (const float4*)(Q + (bh + qrow) * HDd);
    #pragma unroll
    for (int i = 0; i < 16; i++) qreg[i] = qp[i];

    float m = -1e30f, l = 0.0f;
    float4 acc[4] = {{0,0,0,0},{0,0,0,0},{0,0,0,0},{0,0,0,0}};
    const float scale = 0.125f;  // 1/sqrt(64)

    for (int kt = 0; kt <= qt; kt++) {
        __syncthreads();  // protect smem reuse across iterations
        // load K,V tiles: each array 1024 float4, 4 per thread
        #pragma unroll
        for (int i = 0; i < 4; i++) {
            const int idx = tid + i * 256;
            const int r  = idx >> 4;
            const int c4 = idx & 15;
            *(float4*)&Ks[r][c4 * 4] =
                *(const float4*)(K + (bh + kt * 64 + r) * HDd + c4 * 4);
            *(float4*)&Vs[r][c4 * 4] =
                *(const float4*)(V + (bh + kt * 64 + r) * HDd + c4 * 4);
        }
        __syncthreads();

        // Scores for my row's 16 key columns (kcol = 4j + lane4)
        float s[16];
        float tmax = -1e30f;
        const bool diag = (kt == qt);
        #pragma unroll
        for (int j = 0; j < 16; j++) {
            const int kcol = j * 4 + lane4;
            const float4* kp = (const float4*)&Ks[kcol][0];
            float4 sum = {0, 0, 0, 0};
            #pragma unroll
            for (int kk = 0; kk < 16; kk++) {
                float4 k4 = kp[kk];
                sum.x += qreg[kk].x * k4.x;
                sum.y += qreg[kk].y * k4.y;
                sum.z += qreg[kk].z * k4.z;
                sum.w += qreg[kk].w * k4.w;
            }
            float sv = ((sum.x + sum.y) + (sum.z + sum.w)) * scale;
            if (diag && (kt * 64 + kcol) > qrow) sv = -1e30f;
            s[j] = sv;
            tmax = fmaxf(tmax, sv);
        }
        // group-of-4 max
        tmax = fmaxf(tmax, __shfl_xor_sync(0xffffffffu, tmax, 1));
        tmax = fmaxf(tmax, __shfl_xor_sync(0xffffffffu, tmax, 2));

        const float mnew = fmaxf(m, tmax);
        const float corr = expf(m - mnew);
        float lsum = 0.0f;
        #pragma unroll
        for (int j = 0; j < 16; j++) {
            const float p = expf(s[j] - mnew);
            Ps[row][j * 4 + lane4] = p;
            lsum += p;
        }
        lsum += __shfl_xor_sync(0xffffffffu, lsum, 1);
        lsum += __shfl_xor_sync(0xffffffffu, lsum, 2);
        l = l * corr + lsum;
        m = mnew;
        #pragma unroll
        for (int dj = 0; dj < 4; dj++) {
            acc[dj].x *= corr; acc[dj].y *= corr;
            acc[dj].z *= corr; acc[dj].w *= corr;
        }
        __syncwarp();  // Ps writes visible within the warp (row groups are warp-local)

        // acc[dim] += sum_j P[row][j] * V[j][dim];  dims = dj*16 + lane4*4 .. +3
        #pragma unroll 4
        for (int j = 0; j < 64; j++) {
            const float p = Ps[row][j];
            #pragma unroll
            for (int dj = 0; dj < 4; dj++) {
                float4 v4 = *(const float4*)&Vs[j][dj * 16 + lane4 * 4];
                acc[dj].x += p * v4.x;
                acc[dj].y += p * v4.y;
                acc[dj].z += p * v4.z;
                acc[dj].w += p * v4.w;
            }
        }
    }

    const float inv_l = 1.0f / l;
    const size_t ybase = ((size_t)(b * Tsz) + qrow) * Csz + h * HDd;
    #pragma unroll
    for (int dj = 0; dj < 4; dj++) {
        float4 o = acc[dj];
        o.x *= inv_l; o.y *= inv_l; o.z *= inv_l; o.w *= inv_l;
        *(float4*)&Y[ybase + dj * 16 + lane4 * 4] = o;
    }
}

// ---------------------------------------------------------------------------
extern "C" void kernel_launch(void* const* d_in, const int* in_sizes, int n_in,
                              void* d_out, int out_size) {
    (void)in_sizes; (void)n_in; (void)out_size;
    const float* x      = (const float*)d_in[0];
    const float* w_attn = (const float*)d_in[1];
    const float* b_attn = (const float*)d_in[2];
    const float* w_proj = (const float*)d_in[3];
    const float* b_proj = (const float*)d_in[4];
    float* out = (float*)d_out;

    float *p_qkv, *p_q, *p_k, *p_v, *p_y;
    cudaGetSymbolAddress((void**)&p_qkv, g_qkv);
    cudaGetSymbolAddress((void**)&p_q,   g_q);
    cudaGetSymbolAddress((void**)&p_k,   g_k);
    cudaGetSymbolAddress((void**)&p_v,   g_v);
    cudaGetSymbolAddress((void**)&p_y,   g_y);

    const int M = Bsz * Tsz;  // 4096

    // 1) QKV = x @ w_attn + b_attn   [4096, 3072]
    sgemm_bias<<<dim3(3 * Csz / 64, M / 64), 256>>>(
        x, w_attn, b_attn, p_qkv, M, 3 * Csz, Csz);

    // 2) RoPE + split + transpose
    rope_split_kernel<<<(Bsz * Tsz * Hn * 32) / 256, 256>>>(p_qkv);

    // 3) Flash attention
    const int smem_bytes = (2 * 64 * KV_PAD + 64 * P_PAD) * sizeof(float); // 51456
    cudaFuncSetAttribute(flash_attn_kernel,
                         cudaFuncAttributeMaxDynamicSharedMemorySize, smem_bytes);
    flash_attn_kernel<<<dim3(Tsz / 64, Hn, Bsz), 256, smem_bytes>>>(
        p_q, p_k, p_v, p_y);

    // 4) out = y @ w_proj + b_proj   [4096, 1024]
    sgemm_bias<<<dim3(Csz / 64, M / 64), 256>>>(
        p_y, w_proj, b_proj, out, M, Csz, Csz);
}

// round 2
// speedup vs baseline: 1.5207x; 1.5207x over previous
#include <cuda_runtime.h>
#include <math.h>

#define Bsz 2
#define Tsz 2048
#define Csz 1024
#define Hn  16
#define HDd 64

// Scratch (static device arrays — allocation-free per harness rules)
__device__ float g_qkv[Bsz * Tsz * 3 * Csz];      // [B*T, 3C]
__device__ float g_q[Bsz * Hn * Tsz * HDd];       // [B,H,T,HD] rope'd
__device__ float g_k[Bsz * Hn * Tsz * HDd];
__device__ float g_v[Bsz * Hn * Tsz * HDd];
__device__ float g_y[Bsz * Tsz * Csz];            // [B,T,C] attention out

// ---------------------------------------------------------------------------
// SGEMM: C[M,N] = A[M,K] @ B[K,N] + bias[N]
// 128x128 block tile, BK=16, 256 threads, 8x8 register micro-tile.
// ---------------------------------------------------------------------------
__global__ __launch_bounds__(256, 2)
void sgemm128(const float* __restrict__ A,
              const float* __restrict__ Bm,
              const float* __restrict__ bias,
              float* __restrict__ Cm,
              int M, int N, int K) {
    __shared__ float As[16][132];   // A tile transposed: As[k][m]
    __shared__ float Bs[16][132];   // B tile natural:    Bs[k][n] (128 used)

    const int tid = threadIdx.x;
    const int tx = tid & 15;
    const int ty = tid >> 4;
    const int m0 = blockIdx.y * 128;
    const int n0 = blockIdx.x * 128;

    float acc[8][8] = {};

    for (int k0 = 0; k0 < K; k0 += 16) {
        // A tile: 128 rows x 16 cols = 512 float4, 2 per thread, store transposed
        #pragma unroll
        for (int i = 0; i < 2; i++) {
            const int idx = tid + i * 256;
            const int row = idx >> 2;
            const int c4  = idx & 3;
            float4 a = *(const float4*)&A[(size_t)(m0 + row) * K + k0 + c4 * 4];
            As[c4 * 4 + 0][row] = a.x;
            As[c4 * 4 + 1][row] = a.y;
            As[c4 * 4 + 2][row] = a.z;
            As[c4 * 4 + 3][row] = a.w;
        }
        // B tile: 16 rows x 128 cols = 512 float4, 2 per thread
        #pragma unroll
        for (int i = 0; i < 2; i++) {
            const int idx = tid + i * 256;
            const int br  = idx >> 5;
            const int bc4 = idx & 31;
            *(float4*)&Bs[br][bc4 * 4] =
                *(const float4*)&Bm[(size_t)(k0 + br) * N + n0 + bc4 * 4];
        }
        __syncthreads();

        #pragma unroll
        for (int kk = 0; kk < 16; kk++) {
            float av[8], bv[8];
            float4 a0 = *(const float4*)&As[kk][ty * 8];
            float4 a1 = *(const float4*)&As[kk][ty * 8 + 4];
            float4 b0 = *(const float4*)&Bs[kk][tx * 8];
            float4 b1 = *(const float4*)&Bs[kk][tx * 8 + 4];
            av[0]=a0.x; av[1]=a0.y; av[2]=a0.z; av[3]=a0.w;
            av[4]=a1.x; av[5]=a1.y; av[6]=a1.z; av[7]=a1.w;
            bv[0]=b0.x; bv[1]=b0.y; bv[2]=b0.z; bv[3]=b0.w;
            bv[4]=b1.x; bv[5]=b1.y; bv[6]=b1.z; bv[7]=b1.w;
            #pragma unroll
            for (int i = 0; i < 8; i++)
                #pragma unroll
                for (int j = 0; j < 8; j++)
                    acc[i][j] += av[i] * bv[j];
        }
        __syncthreads();
    }

    float4 bb0 = *(const float4*)&bias[n0 + tx * 8];
    float4 bb1 = *(const float4*)&bias[n0 + tx * 8 + 4];
    float bv[8] = {bb0.x, bb0.y, bb0.z, bb0.w, bb1.x, bb1.y, bb1.z, bb1.w};
    #pragma unroll
    for (int i = 0; i < 8; i++) {
        float4 o0, o1;
        o0.x = acc[i][0] + bv[0]; o0.y = acc[i][1] + bv[1];
        o0.z = acc[i][2] + bv[2]; o0.w = acc[i][3] + bv[3];
        o1.x = acc[i][4] + bv[4]; o1.y = acc[i][5] + bv[5];
        o1.z = acc[i][6] + bv[6]; o1.w = acc[i][7] + bv[7];
        float* cp = &Cm[(size_t)(m0 + ty * 8 + i) * N + n0 + tx * 8];
        *(float4*)cp = o0;
        *(float4*)(cp + 4) = o1;
    }
}

// ---------------------------------------------------------------------------
// RoPE + split + transpose: g_qkv[B*T,3C] -> g_q/g_k (rope'd), g_v  [B,H,T,HD]
// ---------------------------------------------------------------------------
__global__ void rope_split_kernel(const float* __restrict__ qkv) {
    const int idx = blockIdx.x * blockDim.x + threadIdx.x;
    const int d2 = idx & 31;
    const int h  = (idx >> 5) & 15;
    const int t  = (idx >> 9) & 2047;
    const int b  = idx >> 20;

    const float* base = qkv + (size_t)(b * Tsz + t) * (3 * Csz);
    const int off = h * HDd + d2;

    const float qf = base[off],           qs = base[off + 32];
    const float kf = base[Csz + off],     ks = base[Csz + off + 32];
    const float vf = base[2 * Csz + off], vs = base[2 * Csz + off + 32];

    const float inv_ts = powf(10000.0f, -(float)d2 * (1.0f / 32.0f));
    const float ang = (float)t * inv_ts;
    float sn, cs;
    sincosf(ang, &sn, &cs);

    const size_t o = (size_t)((b * Hn + h) * Tsz + t) * HDd + d2;
    g_q[o]      = qf * cs - qs * sn;
    g_q[o + 32] = qs * cs + qf * sn;
    g_k[o]      = kf * cs - ks * sn;
    g_k[o + 32] = ks * cs + kf * sn;
    g_v[o]      = vf;
    g_v[o + 32] = vs;
}

// ---------------------------------------------------------------------------
// Flash attention (fp32, online softmax, causal), register-tiled GEMMs.
// 256 threads = 16x16; 64x64 Q/K tiles; 4x4 micro-tile per thread.
// GEMM1: S = Q@K^T from Qt[d][r], Kt[d][c] smem (2 LDS.128 / 16 FMA).
// GEMM2: O += P@V, P natural in smem (scalar broadcast reads), V natural.
// ---------------------------------------------------------------------------
#define FP 68   // padded row stride (floats), 16B-aligned

__global__ __launch_bounds__(256, 2)
void flash_attn_kernel(const float* __restrict__ Q,
                       const float* __restrict__ K,
                       const float* __restrict__ V,
                       float* __restrict__ Y) {
    extern __shared__ float sm[];
    float (*Qt)[FP] = (float(*)[FP])sm;                 // Q^T: Qt[d][r]
    float (*Kt)[FP] = (float(*)[FP])(sm + 64 * FP);     // K^T: Kt[d][c]
    float (*Vs)[FP] = (float(*)[FP])(sm + 2 * 64 * FP); // V:   Vs[j][d]
    float (*Ps)[FP] = (float(*)[FP])(sm + 3 * 64 * FP); // P:   Ps[r][c]

    const int tid = threadIdx.x;
    const int tx = tid & 15;
    const int ty = tid >> 4;
    const int qt = gridDim.x - 1 - blockIdx.x;   // long blocks first
    const int h  = blockIdx.y;
    const int b  = blockIdx.z;

    const size_t bh = (size_t)(b * Hn + h) * Tsz;

    // Load Q tile transposed
    #pragma unroll
    for (int i = 0; i < 4; i++) {
        const int idx = tid + i * 256;
        const int r  = idx >> 4;
        const int c4 = idx & 15;
        float4 q = *(const float4*)&Q[(bh + qt * 64 + r) * HDd + c4 * 4];
        Qt[c4 * 4 + 0][r] = q.x;
        Qt[c4 * 4 + 1][r] = q.y;
        Qt[c4 * 4 + 2][r] = q.z;
        Qt[c4 * 4 + 3][r] = q.w;
    }

    float m[4] = {-1e30f, -1e30f, -1e30f, -1e30f};
    float l[4] = {};
    float acc[4][4] = {};
    const int rbase = ty * 4;
    const int cbase = tx * 4;

    for (int kt = 0; kt <= qt; kt++) {
        __syncthreads();  // Kt/Vs safe to overwrite; Qt visible (first iter)
        // Load K tile transposed + V tile natural
        #pragma unroll
        for (int i = 0; i < 4; i++) {
            const int idx = tid + i * 256;
            const int r  = idx >> 4;
            const int c4 = idx & 15;
            float4 k = *(const float4*)&K[(bh + kt * 64 + r) * HDd + c4 * 4];
            Kt[c4 * 4 + 0][r] = k.x;
            Kt[c4 * 4 + 1][r] = k.y;
            Kt[c4 * 4 + 2][r] = k.z;
            Kt[c4 * 4 + 3][r] = k.w;
            *(float4*)&Vs[r][c4 * 4] =
                *(const float4*)&V[(bh + kt * 64 + r) * HDd + c4 * 4];
        }
        __syncthreads();

        // GEMM1: S[4][4]
        float s[4][4] = {};
        #pragma unroll
        for (int kk = 0; kk < 64; kk++) {
            float4 a4 = *(const float4*)&Qt[kk][rbase];
            float4 b4 = *(const float4*)&Kt[kk][cbase];
            float av[4] = {a4.x, a4.y, a4.z, a4.w};
            float bv[4] = {b4.x, b4.y, b4.z, b4.w};
            #pragma unroll
            for (int i = 0; i < 4; i++)
                #pragma unroll
                for (int j = 0; j < 4; j++)
                    s[i][j] += av[i] * bv[j];
        }

        // Scale + causal mask (diagonal tile only: local compare valid)
        const bool diag = (kt == qt);
        #pragma unroll
        for (int i = 0; i < 4; i++)
            #pragma unroll
            for (int j = 0; j < 4; j++) {
                float sv = s[i][j] * 0.125f;
                if (diag && (cbase + j) > (rbase + i)) sv = -1e30f;
                s[i][j] = sv;
            }

        // Online softmax (row reductions across the 16-lane tx group)
        #pragma unroll
        for (int i = 0; i < 4; i++) {
            float tm = fmaxf(fmaxf(s[i][0], s[i][1]), fmaxf(s[i][2], s[i][3]));
            tm = fmaxf(tm, __shfl_xor_sync(0xffffffffu, tm, 1));
            tm = fmaxf(tm, __shfl_xor_sync(0xffffffffu, tm, 2));
            tm = fmaxf(tm, __shfl_xor_sync(0xffffffffu, tm, 4));
            tm = fmaxf(tm, __shfl_xor_sync(0xffffffffu, tm, 8));
            const float mn = fmaxf(m[i], tm);
            const float corr = __expf(m[i] - mn);
            float sum = 0.0f;
            #pragma unroll
            for (int j = 0; j < 4; j++) {
                const float p = __expf(s[i][j] - mn);
                Ps[rbase + i][cbase + j] = p;
                sum += p;
            }
            sum += __shfl_xor_sync(0xffffffffu, sum, 1);
            sum += __shfl_xor_sync(0xffffffffu, sum, 2);
            sum += __shfl_xor_sync(0xffffffffu, sum, 4);
            sum += __shfl_xor_sync(0xffffffffu, sum, 8);
            l[i] = l[i] * corr + sum;
            m[i] = mn;
            acc[i][0] *= corr; acc[i][1] *= corr;
            acc[i][2] *= corr; acc[i][3] *= corr;
        }
        __syncthreads();

        // GEMM2: acc[i][j] += sum_kk P[rbase+i][kk] * V[kk][cbase+j]
        #pragma unroll
        for (int kk = 0; kk < 64; kk++) {
            float4 b4 = *(const float4*)&Vs[kk][cbase];
            float bv[4] = {b4.x, b4.y, b4.z, b4.w};
            #pragma unroll
            for (int i = 0; i < 4; i++) {
                const float p = Ps[rbase + i][kk];  // broadcast within tx group
                acc[i][0] += p * bv[0];
                acc[i][1] += p * bv[1];
                acc[i][2] += p * bv[2];
                acc[i][3] += p * bv[3];
            }
        }
    }

    // Epilogue
    #pragma unroll
    for (int i = 0; i < 4; i++) {
        const float inv = 1.0f / l[i];
        float4 o;
        o.x = acc[i][0] * inv; o.y = acc[i][1] * inv;
        o.z = acc[i][2] * inv; o.w = acc[i][3] * inv;
        const size_t yoff =
            ((size_t)(b * Tsz) + qt * 64 + rbase + i) * Csz + h * HDd + cbase;
        *(float4*)&Y[yoff] = o;
    }
}

// ---------------------------------------------------------------------------
extern "C" void kernel_launch(void* const* d_in, const int* in_sizes, int n_in,
                              void* d_out, int out_size) {
    (void)in_sizes; (void)n_in; (void)out_size;
    const float* x      = (const float*)d_in[0];
    const float* w_attn = (const float*)d_in[1];
    const float* b_attn = (const float*)d_in[2];
    const float* w_proj = (const float*)d_in[3];
    const float* b_proj = (const float*)d_in[4];
    float* out = (float*)d_out;

    float *p_qkv, *p_q, *p_k, *p_v, *p_y;
    cudaGetSymbolAddress((void**)&p_qkv, g_qkv);
    cudaGetSymbolAddress((void**)&p_q,   g_q);
    cudaGetSymbolAddress((void**)&p_k,   g_k);
    cudaGetSymbolAddress((void**)&p_v,   g_v);
    cudaGetSymbolAddress((void**)&p_y,   g_y);

    const int M = Bsz * Tsz;  // 4096

    // 1) QKV = x @ w_attn + b_attn   [4096, 3072]
    sgemm128<<<dim3(3 * Csz / 128, M / 128), 256>>>(
        x, w_attn, b_attn, p_qkv, M, 3 * Csz, Csz);

    // 2) RoPE + split + transpose
    rope_split_kernel<<<(Bsz * Tsz * Hn * 32) / 256, 256>>>(p_qkv);

    // 3) Flash attention
    const int smem_bytes = 4 * 64 * FP * sizeof(float);  // 69632
    cudaFuncSetAttribute(flash_attn_kernel,
                         cudaFuncAttributeMaxDynamicSharedMemorySize, smem_bytes);
    flash_attn_kernel<<<dim3(Tsz / 64, Hn, Bsz), 256, smem_bytes>>>(
        p_q, p_k, p_v, p_y);

    // 4) out = y @ w_proj + b_proj   [4096, 1024]
    sgemm128<<<dim3(Csz / 128, M / 128), 256>>>(
        p_y, w_proj, b_proj, out, M, Csz, Csz);
}